// round 7
// baseline (speedup 1.0000x reference)
#include <cuda_runtime.h>
#include <cuda_fp16.h>
#include <math.h>
#include <stdint.h>

// ---------------------------------------------------------------------------
// Problem constants
// ---------------------------------------------------------------------------
#define NV 16384   // encoded vectors
#define DD 256     // embedding dim
#define KC 4096    // codebook size

#define BM 128
#define BN 128
#define NTILES (KC / BN)     // 32

// SMEM tile images: 128 rows x 512 B (256 halves), 16B units xor-swizzled
#define TILE_BYTES 65536
#define SMEM_A  0
#define SMEM_B0 65536
#define SMEM_B1 131072
#define SMEM_BAR 196608
#define SMEM_REQ (196608 + 64)

// ---------------------------------------------------------------------------
// Scratch (no allocations allowed). Swizzled 128-row tile images:
// half index = tile*32768 + row_in_tile*256 + ((c16 ^ (row&7)) * 8) + e
// ---------------------------------------------------------------------------
__device__ __half g_zehi16[NV * DD];
__device__ __half g_cbhi16[KC * DD];
__device__ float  g_cn2[KC];          // 0.5 * ||cb_k||^2
__device__ int    g_counts[KC];
__device__ float  g_partials[128];
__device__ int    g_done;             // last-CTA election counter (reset each launch)

// ---------------------------------------------------------------------------
// PTX helpers (sm_80/90-base features only; NO 'a'-gated instructions)
// ---------------------------------------------------------------------------
__device__ __forceinline__ uint32_t smem_u32(const void* p) {
    uint32_t a;
    asm("{ .reg .u64 t; cvta.to.shared.u64 t, %1; cvt.u32.u64 %0, t; }" : "=r"(a) : "l"(p));
    return a;
}

#define MBARRIER_INIT(addr, cnt) \
    asm volatile("mbarrier.init.shared.b64 [%0], %1;" :: "r"((uint32_t)(addr)), "r"((uint32_t)(cnt)) : "memory")
#define MBARRIER_EXPECT_TX(addr, bytes) \
    asm volatile("mbarrier.arrive.expect_tx.shared.b64 _, [%0], %1;" \
                 :: "r"((uint32_t)(addr)), "r"((uint32_t)(bytes)) : "memory")

#define MBARRIER_WAIT_PARITY(mbar_smem_addr, phase_parity) do { \
    uint32_t _mbar = (uint32_t)(mbar_smem_addr); \
    uint32_t _parity = (uint32_t)(phase_parity); \
    uint32_t _done; \
    asm volatile( \
        "{\n\t" \
        ".reg .pred p;\n\t" \
        "mbarrier.try_wait.parity.acquire.cta.shared::cta.b64 p, [%1], %2;\n\t" \
        "selp.b32 %0, 1, 0, p;\n\t" \
        "}" \
        : "=r"(_done) : "r"(_mbar), "r"(_parity) : "memory"); \
    if (!_done) { \
        asm volatile( \
            "{\n\t" \
            ".reg .pred P1;\n\t" \
            "WAIT_LOOP_%=:\n\t" \
            "mbarrier.try_wait.parity.acquire.cta.shared::cta.b64 P1, [%0], %1, 0x989680;\n\t" \
            "@P1 bra.uni WAIT_DONE_%=;\n\t" \
            "bra.uni WAIT_LOOP_%=;\n\t" \
            "WAIT_DONE_%=:\n\t" \
            "}" \
            :: "r"(_mbar), "r"(_parity) : "memory"); \
    } \
} while (0)

__device__ __forceinline__ void bulk_ld(uint32_t dst, const void* src, uint32_t bytes, uint32_t mbar) {
    asm volatile(
        "cp.async.bulk.shared::cluster.global.mbarrier::complete_tx::bytes [%0], [%1], %2, [%3];"
        :: "r"(dst), "l"(src), "r"(bytes), "r"(mbar) : "memory");
}

#define LDMX4(r, addr) \
    asm volatile("ldmatrix.sync.aligned.m8n8.x4.shared.b16 {%0,%1,%2,%3}, [%4];" \
        : "=r"((r)[0]), "=r"((r)[1]), "=r"((r)[2]), "=r"((r)[3]) : "r"(addr))

// fp16-accumulate MMA: D = A*B + D, D/C packed f16x2 (2 regs)
#define MMAF16(d, a, b0v, b1v) \
    asm volatile("mma.sync.aligned.m16n8k16.row.col.f16.f16.f16.f16 " \
        "{%0,%1}, {%2,%3,%4,%5}, {%6,%7}, {%0,%1};" \
        : "+r"((d)[0]), "+r"((d)[1]) \
        : "r"((a)[0]), "r"((a)[1]), "r"((a)[2]), "r"((a)[3]), "r"(b0v), "r"(b1v))

// ---------------------------------------------------------------------------
// Kernel 1 (fused): fp16 convert into swizzled tile images  +  codebook
// half-norms + zero counts. Blocks [0,2560): convert; [2560,3072): norms.
// ---------------------------------------------------------------------------
__global__ void prep_kernel(const float* __restrict__ ze, const float* __restrict__ cb) {
    if (blockIdx.x < 2560) {
        const int u = blockIdx.x * 256 + threadIdx.x;
        const int ZU = NV * 32;                         // 16B units in ze
        const float4* src; __half* dst; int v;
        if (u < ZU) { src = (const float4*)ze; dst = g_zehi16; v = u; }
        else        { src = (const float4*)cb; dst = g_cbhi16; v = u - ZU; }
        const int row = v >> 5, c16 = v & 31;
        const int tile = row >> 7, rin = row & 127;
        float4 f0 = src[v * 2], f1 = src[v * 2 + 1];
        __half2 h0 = __floats2half2_rn(f0.x, f0.y);
        __half2 h1 = __floats2half2_rn(f0.z, f0.w);
        __half2 h2 = __floats2half2_rn(f1.x, f1.y);
        __half2 h3 = __floats2half2_rn(f1.z, f1.w);
        uint4 w;
        w.x = *(uint32_t*)&h0; w.y = *(uint32_t*)&h1;
        w.z = *(uint32_t*)&h2; w.w = *(uint32_t*)&h3;
        const size_t d = (size_t)tile * 32768 + rin * 256 + ((c16 ^ (rin & 7)) * 8);
        *(uint4*)(dst + d) = w;
    } else {
        const int gid  = (blockIdx.x - 2560) * 256 + threadIdx.x;   // 512x256 = 4096 warps
        const int code = gid >> 5;
        const int lane = gid & 31;
        const float* row = cb + (size_t)code * DD;
        float s = 0.f;
#pragma unroll
        for (int i = 0; i < DD; i += 32) { float v = row[i + lane]; s += v * v; }
#pragma unroll
        for (int off = 16; off; off >>= 1) s += __shfl_down_sync(0xffffffffu, s, off);
        if (lane == 0) g_cn2[code] = 0.5f * s;
        if (gid < KC) g_counts[gid] = 0;
    }
}

// ---------------------------------------------------------------------------
// Kernel 2: fp16-accum mma GEMM + per-row approx top-2 -> global top-4 ->
// exact fp32 refine; fused gather/loss; last CTA computes final scalars.
//   A tile resident in SMEM; B tiles streamed via cp.async.bulk (double buf).
//   8 warps: 2(m) x 4(n), warp tile 64x32.
//   score = dot - 0.5*||c||^2 (maximize). f16 accum per K=64 chunk, promoted
//   to fp32 between chunks.
// ---------------------------------------------------------------------------
__global__ void __launch_bounds__(256, 1) argmin_kernel(
    const float* __restrict__ ze, const float* __restrict__ cb,
    float* __restrict__ out)
{
    extern __shared__ char smraw[];
    const uint32_t smb = smem_u32(smraw);
    const uint32_t barA  = smb + SMEM_BAR;
    const uint32_t barB0 = smb + SMEM_BAR + 8;
    const uint32_t barB1 = smb + SMEM_BAR + 16;

    const int tid    = threadIdx.x;
    const int lane   = tid & 31;
    const int wid    = tid >> 5;
    const int warp_m = wid & 1;
    const int warp_n = wid >> 1;
    const int r0     = blockIdx.x * BM;

    if (tid == 0) {
        MBARRIER_INIT(barA, 1);
        MBARRIER_INIT(barB0, 1);
        MBARRIER_INIT(barB1, 1);
    }
    __syncthreads();

    if (tid == 0) {
        MBARRIER_EXPECT_TX(barA, TILE_BYTES);
        bulk_ld(smb + SMEM_A, g_zehi16 + (size_t)blockIdx.x * 32768, TILE_BYTES, barA);
        MBARRIER_EXPECT_TX(barB0, TILE_BYTES);
        bulk_ld(smb + SMEM_B0, g_cbhi16, TILE_BYTES, barB0);
    }

    // ---- per-thread fragment addressing (swizzled image layout) ----
    const int x7   = lane & 7;
    const int a_hi = lane >> 4;
    const int b_hi = (lane >> 3) & 1;
    const uint32_t a_ro = (uint32_t)(warp_m * 64 + (lane & 15)) * 512;
    const uint32_t b_ro = (uint32_t)(warp_n * 32 + ((lane >> 4) << 3) + (lane & 7)) * 512;

    float acc[16][4];
#pragma unroll
    for (int i = 0; i < 16; i++)
#pragma unroll
        for (int j = 0; j < 4; j++) acc[i][j] = 0.f;

    uint32_t fd[16][2];
#pragma unroll
    for (int i = 0; i < 16; i++) { fd[i][0] = 0u; fd[i][1] = 0u; }

    float b1v[8], b2v[8];
    int   b1i[8], b2i[8];
#pragma unroll
    for (int i = 0; i < 8; i++) { b1v[i] = -3.4e38f; b2v[i] = -3.4e38f; b1i[i] = 0; b2i[i] = 1; }

    MBARRIER_WAIT_PARITY(barA, 0);
    int phB[2] = {0, 0};

    for (int nt = 0; nt < NTILES; nt++) {
        const int b = nt & 1;
        if (nt + 1 < NTILES && tid == 0) {
            const uint32_t bar = (b ? barB0 : barB1);
            MBARRIER_EXPECT_TX(bar, TILE_BYTES);
            bulk_ld(smb + (b ? SMEM_B0 : SMEM_B1), g_cbhi16 + (size_t)(nt + 1) * 32768,
                    TILE_BYTES, bar);
        }
        MBARRIER_WAIT_PARITY((b ? barB1 : barB0), phB[b]);
        phB[b] ^= 1;

        const uint32_t aBase = smb + SMEM_A + a_ro;
        const uint32_t bBase = smb + (b ? SMEM_B1 : SMEM_B0) + b_ro;

#pragma unroll
        for (int ks = 0; ks < 16; ks++) {          // 16 k16-steps
            const int c2 = ks * 2;
            uint32_t Af[4][4], Bf[2][4];
            const uint32_t ca  = (uint32_t)(((c2 + a_hi) ^ x7) << 4);
            const uint32_t cbo = (uint32_t)(((c2 + b_hi) ^ x7) << 4);
#pragma unroll
            for (int mt = 0; mt < 4; mt++) LDMX4(Af[mt], aBase + mt * (16 * 512) + ca);
#pragma unroll
            for (int p = 0; p < 2; p++)    LDMX4(Bf[p], bBase + p * (16 * 512) + cbo);
#pragma unroll
            for (int mt = 0; mt < 4; mt++)
#pragma unroll
                for (int ntt = 0; ntt < 4; ntt++)
                    MMAF16(fd[mt * 4 + ntt], Af[mt],
                           Bf[ntt >> 1][(ntt & 1) * 2], Bf[ntt >> 1][(ntt & 1) * 2 + 1]);

            if ((ks & 3) == 3) {   // promote K=64 chunk to fp32, reset f16 accs
#pragma unroll
                for (int t = 0; t < 16; t++) {
                    float2 lo = __half22float2(*(__half2*)&fd[t][0]);
                    float2 hi = __half22float2(*(__half2*)&fd[t][1]);
                    acc[t][0] += lo.x; acc[t][1] += lo.y;
                    acc[t][2] += hi.x; acc[t][3] += hi.y;
                    fd[t][0] = 0u; fd[t][1] = 0u;
                }
            }
        }

        // ---- fold -0.5||c||^2, update per-thread top-2, reset fp32 accs ----
        const int cbase = nt * BN + warp_n * 32 + (lane & 3) * 2;
#pragma unroll
        for (int j = 0; j < 4; j++) {
            const int   c0  = cbase + j * 8;
            const float cn0 = __ldg(g_cn2 + c0);
            const float cn1 = __ldg(g_cn2 + c0 + 1);
#pragma unroll
            for (int mt = 0; mt < 4; mt++) {
                float* a = acc[mt * 4 + j];
                const int rs0 = mt * 2, rs1 = mt * 2 + 1;
                const float v0 = a[0] - cn0, v1 = a[1] - cn1;
                const float v2 = a[2] - cn0, v3 = a[3] - cn1;
                if (v0 > b1v[rs0]) { b2v[rs0] = b1v[rs0]; b2i[rs0] = b1i[rs0]; b1v[rs0] = v0; b1i[rs0] = c0; }
                else if (v0 > b2v[rs0]) { b2v[rs0] = v0; b2i[rs0] = c0; }
                if (v1 > b1v[rs0]) { b2v[rs0] = b1v[rs0]; b2i[rs0] = b1i[rs0]; b1v[rs0] = v1; b1i[rs0] = c0 + 1; }
                else if (v1 > b2v[rs0]) { b2v[rs0] = v1; b2i[rs0] = c0 + 1; }
                if (v2 > b1v[rs1]) { b2v[rs1] = b1v[rs1]; b2i[rs1] = b1i[rs1]; b1v[rs1] = v2; b1i[rs1] = c0; }
                else if (v2 > b2v[rs1]) { b2v[rs1] = v2; b2i[rs1] = c0; }
                if (v3 > b1v[rs1]) { b2v[rs1] = b1v[rs1]; b2i[rs1] = b1i[rs1]; b1v[rs1] = v3; b1i[rs1] = c0 + 1; }
                else if (v3 > b2v[rs1]) { b2v[rs1] = v3; b2i[rs1] = c0 + 1; }
                a[0] = a[1] = a[2] = a[3] = 0.f;
            }
        }
        __syncthreads();
    }

    // ---- cross-thread merge: per-thread top-2 -> global top-4 per row ----
    float* sB4 = (float*)smraw;                    // [128][4 warps][4]
    int*   sI4 = (int*)(smraw + 8192);
    const int g = lane >> 2;

#pragma unroll
    for (int rs = 0; rs < 8; rs++) {
        float lv[4] = {b1v[rs], b2v[rs], -3.4e38f, -3.4e38f};
        int   li[4] = {b1i[rs], b2i[rs], 0, 1};
#pragma unroll
        for (int off = 1; off <= 2; off <<= 1) {
#pragma unroll
            for (int e = 0; e < 4; e++) {
                const float ov = __shfl_xor_sync(0xffffffffu, lv[e], off);
                const int   oi = __shfl_xor_sync(0xffffffffu, li[e], off);
                if (ov > lv[3] || (ov == lv[3] && oi < li[3])) {
                    lv[3] = ov; li[3] = oi;
#pragma unroll
                    for (int p = 3; p > 0; p--)
                        if (lv[p] > lv[p-1] || (lv[p] == lv[p-1] && li[p] < li[p-1])) {
                            float tv = lv[p]; lv[p] = lv[p-1]; lv[p-1] = tv;
                            int   ti = li[p]; li[p] = li[p-1]; li[p-1] = ti;
                        }
                }
            }
        }
        if ((lane & 3) == 0) {
            const int rl = warp_m * 64 + (rs >> 1) * 16 + (rs & 1) * 8 + g;
#pragma unroll
            for (int e = 0; e < 4; e++) {
                sB4[(rl * 4 + warp_n) * 4 + e] = lv[e];
                sI4[(rl * 4 + warp_n) * 4 + e] = li[e];
            }
        }
    }
    __syncthreads();

    float s = 0.f;
    if (tid < 128) {
        float lv[4]; int li[4];
#pragma unroll
        for (int e = 0; e < 4; e++) { lv[e] = sB4[tid * 16 + e]; li[e] = sI4[tid * 16 + e]; }
#pragma unroll
        for (int w = 1; w < 4; w++)
#pragma unroll
            for (int e = 0; e < 4; e++) {
                const float ov = sB4[(tid * 4 + w) * 4 + e];
                const int   oi = sI4[(tid * 4 + w) * 4 + e];
                if (ov > lv[3] || (ov == lv[3] && oi < li[3])) {
                    lv[3] = ov; li[3] = oi;
#pragma unroll
                    for (int p = 3; p > 0; p--)
                        if (lv[p] > lv[p-1] || (lv[p] == lv[p-1] && li[p] < li[p-1])) {
                            float tv = lv[p]; lv[p] = lv[p-1]; lv[p-1] = tv;
                            int   ti = li[p]; li[p] = li[p-1]; li[p-1] = ti;
                        }
                }
            }

        // ---- exact fp32 refine of 4 candidates (lowest dist, then lowest idx) ----
        const int row = r0 + tid;
        const float4* zr = (const float4*)(ze + (size_t)row * DD);
        const float4* cr0 = (const float4*)(cb + (size_t)li[0] * DD);
        const float4* cr1 = (const float4*)(cb + (size_t)li[1] * DD);
        const float4* cr2 = (const float4*)(cb + (size_t)li[2] * DD);
        const float4* cr3 = (const float4*)(cb + (size_t)li[3] * DD);
        float d0 = 0.f, d1 = 0.f, d2 = 0.f, d3 = 0.f;
#pragma unroll 2
        for (int j = 0; j < DD / 4; j++) {
            const float4 z = zr[j];
            float4 c; float t;
            c = cr0[j];
            t = z.x - c.x; d0 += t * t; t = z.y - c.y; d0 += t * t;
            t = z.z - c.z; d0 += t * t; t = z.w - c.w; d0 += t * t;
            c = cr1[j];
            t = z.x - c.x; d1 += t * t; t = z.y - c.y; d1 += t * t;
            t = z.z - c.z; d1 += t * t; t = z.w - c.w; d1 += t * t;
            c = cr2[j];
            t = z.x - c.x; d2 += t * t; t = z.y - c.y; d2 += t * t;
            t = z.z - c.z; d2 += t * t; t = z.w - c.w; d2 += t * t;
            c = cr3[j];
            t = z.x - c.x; d3 += t * t; t = z.y - c.y; d3 += t * t;
            t = z.z - c.z; d3 += t * t; t = z.w - c.w; d3 += t * t;
        }
        float dl = d0; int ix = li[0];
        if (d1 < dl || (d1 == dl && li[1] < ix)) { dl = d1; ix = li[1]; }
        if (d2 < dl || (d2 == dl && li[2] < ix)) { dl = d2; ix = li[2]; }
        if (d3 < dl || (d3 == dl && li[3] < ix)) { dl = d3; ix = li[3]; }

        out[row] = (float)ix;
        atomicAdd(&g_counts[ix], 1);
        s = dl;

        const float4* cr = (const float4*)(cb + (size_t)ix * DD);
        float4* orow = (float4*)(out + NV + (size_t)row * DD);
#pragma unroll 4
        for (int j = 0; j < DD / 4; j++) orow[j] = cr[j];
    }
    __syncthreads();
    float* red = (float*)(smraw + 16384);
    red[tid] = s;
    __syncthreads();
    for (int off = 128; off; off >>= 1) {
        if (tid < off) red[tid] += red[tid + off];
        __syncthreads();
    }
    if (tid == 0) g_partials[blockIdx.x] = red[0];

    // ================= last-CTA finalize (losses + perplexity) =================
    __shared__ int sLast;
    __threadfence();
    if (tid == 0) sLast = (atomicAdd(&g_done, 1) == (NV / BM) - 1);
    __syncthreads();
    if (!sLast) return;
    __threadfence();   // acquire: all CTAs' partials/counts visible

    float ls = (tid < 128) ? g_partials[tid] : 0.f;
    red[tid] = ls;
    __syncthreads();
    for (int off = 128; off; off >>= 1) {
        if (tid < off) red[tid] += red[tid + off];
        __syncthreads();
    }
    if (tid == 0) {
        const float loss = red[0] / (float)((size_t)NV * DD);
        out[(size_t)NV + (size_t)NV * DD + 0] = loss;
        out[(size_t)NV + (size_t)NV * DD + 1] = loss;
    }
    __syncthreads();

    float e = 0.f;
    for (int k = tid; k < KC; k += 256) {
        const float p = (float)g_counts[k] * 0.1f;
        e += p * logf(p + 1e-10f);
    }
    red[tid] = e;
    __syncthreads();
    for (int off = 128; off; off >>= 1) {
        if (tid < off) red[tid] += red[tid + off];
        __syncthreads();
    }
    if (tid == 0) {
        out[(size_t)NV + (size_t)NV * DD + 2] = expf(-red[0]);
        g_done = 0;   // reset for next graph replay
    }
}

// ---------------------------------------------------------------------------
extern "C" void kernel_launch(void* const* d_in, const int* in_sizes, int n_in,
                              void* d_out, int out_size)
{
    const float* ze = (const float*)d_in[0];
    const float* cb = (const float*)d_in[1];
    float* out = (float*)d_out;

    cudaFuncSetAttribute(argmin_kernel,
                         cudaFuncAttributeMaxDynamicSharedMemorySize, SMEM_REQ);

    prep_kernel<<<2560 + 512, 256>>>(ze, cb);
    argmin_kernel<<<NV / BM, 256, SMEM_REQ>>>(ze, cb, out);
}

// round 12
// speedup vs baseline: 1.3687x; 1.3687x over previous
#include <cuda_runtime.h>
#include <cuda_fp16.h>
#include <math.h>
#include <stdint.h>

// ---------------------------------------------------------------------------
// Problem constants
// ---------------------------------------------------------------------------
#define NV 16384   // encoded vectors
#define DD 256     // embedding dim
#define KC 4096    // codebook size

#define BM 128
#define BN 128
#define NTILES (KC / BN)     // 32
#define NCTAS  (NV / BM)     // 128

// SMEM tile images: 128 rows x 512 B (256 halves), 16B units xor-swizzled
#define TILE_BYTES 65536
#define SMEM_A  0
#define SMEM_B0 65536
#define SMEM_B1 131072
#define SMEM_BAR 196608
#define SMEM_REQ (196608 + 64)

// ---------------------------------------------------------------------------
// Scratch (no allocations allowed). Swizzled 128-row tile images:
// half index = tile*32768 + row_in_tile*256 + ((c16 ^ (row&7)) * 8) + e
// ---------------------------------------------------------------------------
__device__ __half g_zehi16[NV * DD];
__device__ __half g_cbhi16[KC * DD];
__device__ float  g_cn2[KC];          // 0.5 * ||cb_k||^2
__device__ int    g_counts[KC];
__device__ float  g_partials[NCTAS];
__device__ int    g_done;             // last-CTA election counter (reset each launch)

// ---------------------------------------------------------------------------
// PTX helpers (sm_80/90-base features only; NO 'a'-gated instructions)
// ---------------------------------------------------------------------------
__device__ __forceinline__ uint32_t smem_u32(const void* p) {
    uint32_t a;
    asm("{ .reg .u64 t; cvta.to.shared.u64 t, %1; cvt.u32.u64 %0, t; }" : "=r"(a) : "l"(p));
    return a;
}

#define MBARRIER_INIT(addr, cnt) \
    asm volatile("mbarrier.init.shared.b64 [%0], %1;" :: "r"((uint32_t)(addr)), "r"((uint32_t)(cnt)) : "memory")
#define MBARRIER_EXPECT_TX(addr, bytes) \
    asm volatile("mbarrier.arrive.expect_tx.shared.b64 _, [%0], %1;" \
                 :: "r"((uint32_t)(addr)), "r"((uint32_t)(bytes)) : "memory")

#define MBARRIER_WAIT_PARITY(mbar_smem_addr, phase_parity) do { \
    uint32_t _mbar = (uint32_t)(mbar_smem_addr); \
    uint32_t _parity = (uint32_t)(phase_parity); \
    uint32_t _done; \
    asm volatile( \
        "{\n\t" \
        ".reg .pred p;\n\t" \
        "mbarrier.try_wait.parity.acquire.cta.shared::cta.b64 p, [%1], %2;\n\t" \
        "selp.b32 %0, 1, 0, p;\n\t" \
        "}" \
        : "=r"(_done) : "r"(_mbar), "r"(_parity) : "memory"); \
    if (!_done) { \
        asm volatile( \
            "{\n\t" \
            ".reg .pred P1;\n\t" \
            "WAIT_LOOP_%=:\n\t" \
            "mbarrier.try_wait.parity.acquire.cta.shared::cta.b64 P1, [%0], %1, 0x989680;\n\t" \
            "@P1 bra.uni WAIT_DONE_%=;\n\t" \
            "bra.uni WAIT_LOOP_%=;\n\t" \
            "WAIT_DONE_%=:\n\t" \
            "}" \
            :: "r"(_mbar), "r"(_parity) : "memory"); \
    } \
} while (0)

__device__ __forceinline__ void bulk_ld(uint32_t dst, const void* src, uint32_t bytes, uint32_t mbar) {
    asm volatile(
        "cp.async.bulk.shared::cluster.global.mbarrier::complete_tx::bytes [%0], [%1], %2, [%3];"
        :: "r"(dst), "l"(src), "r"(bytes), "r"(mbar) : "memory");
}

#define LDMX4(r, addr) \
    asm volatile("ldmatrix.sync.aligned.m8n8.x4.shared.b16 {%0,%1,%2,%3}, [%4];" \
        : "=r"((r)[0]), "=r"((r)[1]), "=r"((r)[2]), "=r"((r)[3]) : "r"(addr))

#define MMA16816(d, a, b0v, b1v) \
    asm volatile("mma.sync.aligned.m16n8k16.row.col.f32.f16.f16.f32 " \
        "{%0,%1,%2,%3}, {%4,%5,%6,%7}, {%8,%9}, {%0,%1,%2,%3};" \
        : "+f"((d)[0]), "+f"((d)[1]), "+f"((d)[2]), "+f"((d)[3]) \
        : "r"((a)[0]), "r"((a)[1]), "r"((a)[2]), "r"((a)[3]), "r"(b0v), "r"(b1v))

// ---------------------------------------------------------------------------
// Kernel 1 (fused): fp16 convert into swizzled tile images + codebook
// half-norms + zero counts. Blocks [0,2560): convert; [2560,3072): norms.
// ---------------------------------------------------------------------------
__global__ void prep_kernel(const float* __restrict__ ze, const float* __restrict__ cb) {
    if (blockIdx.x < 2560) {
        const int u = blockIdx.x * 256 + threadIdx.x;
        const int ZU = NV * 32;                         // 16B units in ze
        const float4* src; __half* dst; int v;
        if (u < ZU) { src = (const float4*)ze; dst = g_zehi16; v = u; }
        else        { src = (const float4*)cb; dst = g_cbhi16; v = u - ZU; }
        const int row = v >> 5, c16 = v & 31;
        const int tile = row >> 7, rin = row & 127;
        float4 f0 = src[v * 2], f1 = src[v * 2 + 1];
        __half2 h0 = __floats2half2_rn(f0.x, f0.y);
        __half2 h1 = __floats2half2_rn(f0.z, f0.w);
        __half2 h2 = __floats2half2_rn(f1.x, f1.y);
        __half2 h3 = __floats2half2_rn(f1.z, f1.w);
        uint4 w;
        w.x = *(uint32_t*)&h0; w.y = *(uint32_t*)&h1;
        w.z = *(uint32_t*)&h2; w.w = *(uint32_t*)&h3;
        const size_t d = (size_t)tile * 32768 + rin * 256 + ((c16 ^ (rin & 7)) * 8);
        *(uint4*)(dst + d) = w;
    } else {
        const int gid  = (blockIdx.x - 2560) * 256 + threadIdx.x;   // 512x256 = 4096 warps
        const int code = gid >> 5;
        const int lane = gid & 31;
        const float* row = cb + (size_t)code * DD;
        float s = 0.f;
#pragma unroll
        for (int i = 0; i < DD; i += 32) { float v = row[i + lane]; s += v * v; }
#pragma unroll
        for (int off = 16; off; off >>= 1) s += __shfl_down_sync(0xffffffffu, s, off);
        if (lane == 0) g_cn2[code] = 0.5f * s;
        if (gid < KC) g_counts[gid] = 0;
    }
}

// ---------------------------------------------------------------------------
// Kernel 2: fp32-accum mma GEMM (512 threads, 16 warps: 4m x 4n, warp tile
// 32x32) + per-row approx top-2 -> global top-2 -> exact fp32 refine; fused
// gather/loss; last CTA computes final scalars.
//   A tile resident in SMEM; B tiles streamed via cp.async.bulk (double buf).
//   score = dot - 0.5*||c||^2 (maximize) == distance argmin; first-min ties.
// ---------------------------------------------------------------------------
__global__ void __launch_bounds__(512, 1) argmin_kernel(
    const float* __restrict__ ze, const float* __restrict__ cb,
    float* __restrict__ out)
{
    extern __shared__ char smraw[];
    const uint32_t smb = smem_u32(smraw);
    const uint32_t barA  = smb + SMEM_BAR;
    const uint32_t barB0 = smb + SMEM_BAR + 8;
    const uint32_t barB1 = smb + SMEM_BAR + 16;

    const int tid    = threadIdx.x;
    const int lane   = tid & 31;
    const int wid    = tid >> 5;
    const int warp_m = wid & 3;       // 0..3 -> 32 rows each
    const int warp_n = wid >> 2;      // 0..3 -> 32 cols each
    const int r0     = blockIdx.x * BM;

    if (tid == 0) {
        MBARRIER_INIT(barA, 1);
        MBARRIER_INIT(barB0, 1);
        MBARRIER_INIT(barB1, 1);
    }
    __syncthreads();

    if (tid == 0) {
        MBARRIER_EXPECT_TX(barA, TILE_BYTES);
        bulk_ld(smb + SMEM_A, g_zehi16 + (size_t)blockIdx.x * 32768, TILE_BYTES, barA);
        MBARRIER_EXPECT_TX(barB0, TILE_BYTES);
        bulk_ld(smb + SMEM_B0, g_cbhi16, TILE_BYTES, barB0);
    }

    // ---- per-thread fragment addressing (swizzled image layout) ----
    const int x7   = lane & 7;
    const int a_hi = lane >> 4;                      // A ldmatrix c16 select
    const int b_hi = (lane >> 3) & 1;                // B ldmatrix c16 select
    const uint32_t a_ro = (uint32_t)(warp_m * 32 + (lane & 15)) * 512;
    const uint32_t b_ro = (uint32_t)(warp_n * 32 + ((lane >> 4) << 3) + (lane & 7)) * 512;

    float acc[8][4];                                 // 2 m16-tiles x 4 n8-tiles
#pragma unroll
    for (int i = 0; i < 8; i++)
#pragma unroll
        for (int j = 0; j < 4; j++) acc[i][j] = 0.f;

    float b1v[4], b2v[4];                            // 4 row slots/thread
    int   b1i[4], b2i[4];
#pragma unroll
    for (int i = 0; i < 4; i++) { b1v[i] = -3.4e38f; b2v[i] = -3.4e38f; b1i[i] = 0; b2i[i] = 1; }

    MBARRIER_WAIT_PARITY(barA, 0);
    int phB[2] = {0, 0};

    for (int nt = 0; nt < NTILES; nt++) {
        const int b = nt & 1;
        if (nt + 1 < NTILES && tid == 0) {
            const uint32_t bar = (b ? barB0 : barB1);
            MBARRIER_EXPECT_TX(bar, TILE_BYTES);
            bulk_ld(smb + (b ? SMEM_B0 : SMEM_B1), g_cbhi16 + (size_t)(nt + 1) * 32768,
                    TILE_BYTES, bar);
        }
        MBARRIER_WAIT_PARITY((b ? barB1 : barB0), phB[b]);
        phB[b] ^= 1;

        const uint32_t aBase = smb + SMEM_A + a_ro;
        const uint32_t bBase = smb + (b ? SMEM_B1 : SMEM_B0) + b_ro;

#pragma unroll
        for (int ks = 0; ks < 16; ks++) {            // 16 k16-steps
            const int c2 = ks * 2;
            uint32_t Af[2][4], Bf[2][4];
            const uint32_t ca  = (uint32_t)(((c2 + a_hi) ^ x7) << 4);
            const uint32_t cbo = (uint32_t)(((c2 + b_hi) ^ x7) << 4);
#pragma unroll
            for (int mt = 0; mt < 2; mt++) LDMX4(Af[mt], aBase + mt * (16 * 512) + ca);
#pragma unroll
            for (int p = 0; p < 2; p++)    LDMX4(Bf[p], bBase + p * (16 * 512) + cbo);
#pragma unroll
            for (int mt = 0; mt < 2; mt++)
#pragma unroll
                for (int ntt = 0; ntt < 4; ntt++)
                    MMA16816(acc[mt * 4 + ntt], Af[mt],
                             Bf[ntt >> 1][(ntt & 1) * 2], Bf[ntt >> 1][(ntt & 1) * 2 + 1]);
        }

        // ---- fold -0.5||c||^2, update per-thread top-2, reset accs ----
        const int cbase = nt * BN + warp_n * 32 + (lane & 3) * 2;
#pragma unroll
        for (int j = 0; j < 4; j++) {
            const int   c0  = cbase + j * 8;
            const float cn0 = __ldg(g_cn2 + c0);
            const float cn1 = __ldg(g_cn2 + c0 + 1);
#pragma unroll
            for (int mt = 0; mt < 2; mt++) {
                float* a = acc[mt * 4 + j];
                const int rs0 = mt * 2, rs1 = mt * 2 + 1;
                const float v0 = a[0] - cn0, v1 = a[1] - cn1;
                const float v2 = a[2] - cn0, v3 = a[3] - cn1;
                if (v0 > b1v[rs0]) { b2v[rs0] = b1v[rs0]; b2i[rs0] = b1i[rs0]; b1v[rs0] = v0; b1i[rs0] = c0; }
                else if (v0 > b2v[rs0]) { b2v[rs0] = v0; b2i[rs0] = c0; }
                if (v1 > b1v[rs0]) { b2v[rs0] = b1v[rs0]; b2i[rs0] = b1i[rs0]; b1v[rs0] = v1; b1i[rs0] = c0 + 1; }
                else if (v1 > b2v[rs0]) { b2v[rs0] = v1; b2i[rs0] = c0 + 1; }
                if (v2 > b1v[rs1]) { b2v[rs1] = b1v[rs1]; b2i[rs1] = b1i[rs1]; b1v[rs1] = v2; b1i[rs1] = c0; }
                else if (v2 > b2v[rs1]) { b2v[rs1] = v2; b2i[rs1] = c0; }
                if (v3 > b1v[rs1]) { b2v[rs1] = b1v[rs1]; b2i[rs1] = b1i[rs1]; b1v[rs1] = v3; b1i[rs1] = c0 + 1; }
                else if (v3 > b2v[rs1]) { b2v[rs1] = v3; b2i[rs1] = c0 + 1; }
                a[0] = a[1] = a[2] = a[3] = 0.f;
            }
        }
        __syncthreads();   // all threads done reading buffer b before refill
    }

    // ---- cross-thread top-2 merge (quad via shuffle, warp_n groups via smem) ----
    float* sB1 = (float*)smraw;                  // [128][4]
    int*   sI1 = (int*)(smraw + 2048);
    float* sB2 = (float*)(smraw + 4096);
    int*   sI2 = (int*)(smraw + 6144);
    const int g = lane >> 2;

#pragma unroll
    for (int rs = 0; rs < 4; rs++) {
        float v1 = b1v[rs], v2 = b2v[rs];
        int   i1 = b1i[rs], i2 = b2i[rs];
#pragma unroll
        for (int off = 1; off <= 2; off <<= 1) {
            const float o1 = __shfl_xor_sync(0xffffffffu, v1, off);
            const int   oi1 = __shfl_xor_sync(0xffffffffu, i1, off);
            const float o2 = __shfl_xor_sync(0xffffffffu, v2, off);
            const int   oi2 = __shfl_xor_sync(0xffffffffu, i2, off);
            if (o1 > v1) {
                const float n2 = (v1 > o2) ? v1 : o2;
                const int   n2i = (v1 > o2) ? i1 : oi2;
                v2 = n2; i2 = n2i; v1 = o1; i1 = oi1;
            } else if (o1 > v2) { v2 = o1; i2 = oi1; }
        }
        if ((lane & 3) == 0) {
            const int rl = warp_m * 32 + (rs >> 1) * 16 + (rs & 1) * 8 + g;
            sB1[rl * 4 + warp_n] = v1; sI1[rl * 4 + warp_n] = i1;
            sB2[rl * 4 + warp_n] = v2; sI2[rl * 4 + warp_n] = i2;
        }
    }
    __syncthreads();

    float s = 0.f;
    if (tid < 128) {
        float v1 = sB1[tid * 4], v2 = sB2[tid * 4];
        int   i1 = sI1[tid * 4], i2 = sI2[tid * 4];
#pragma unroll
        for (int w = 1; w < 4; w++) {
            const float o1 = sB1[tid * 4 + w], o2 = sB2[tid * 4 + w];
            const int   oi1 = sI1[tid * 4 + w], oi2 = sI2[tid * 4 + w];
            if (o1 > v1) {
                const float n2 = (v1 > o2) ? v1 : o2;
                const int   n2i = (v1 > o2) ? i1 : oi2;
                v2 = n2; i2 = n2i; v1 = o1; i1 = oi1;
            } else if (o1 > v2) { v2 = o1; i2 = oi1; }
        }

        // ---- exact fp32 refine of the two candidates ----
        const int row = r0 + tid;
        const float4* zr = (const float4*)(ze + (size_t)row * DD);
        const float4* c1r = (const float4*)(cb + (size_t)i1 * DD);
        const float4* c2r = (const float4*)(cb + (size_t)i2 * DD);
        float d1 = 0.f, d2 = 0.f;
#pragma unroll 4
        for (int j = 0; j < DD / 4; j++) {
            const float4 z = zr[j], a = c1r[j], bq = c2r[j];
            float t;
            t = z.x - a.x; d1 += t * t;  t = z.y - a.y; d1 += t * t;
            t = z.z - a.z; d1 += t * t;  t = z.w - a.w; d1 += t * t;
            t = z.x - bq.x; d2 += t * t; t = z.y - bq.y; d2 += t * t;
            t = z.z - bq.z; d2 += t * t; t = z.w - bq.w; d2 += t * t;
        }
        int ix; float dl;
        if (d2 < d1 || (d2 == d1 && i2 < i1)) { ix = i2; dl = d2; }
        else                                  { ix = i1; dl = d1; }

        out[row] = (float)ix;
        atomicAdd(&g_counts[ix], 1);
        s = dl;   // squared error for this row == loss partial

        const float4* cr = (const float4*)(cb + (size_t)ix * DD);
        float4* orow = (float4*)(out + NV + (size_t)row * DD);
#pragma unroll 4
        for (int j = 0; j < DD / 4; j++) orow[j] = cr[j];
    }
    __syncthreads();
    float* red = (float*)(smraw + 8192);   // [512]
    red[tid] = s;
    __syncthreads();
    for (int off = 256; off; off >>= 1) {
        if (tid < off) red[tid] += red[tid + off];
        __syncthreads();
    }
    if (tid == 0) g_partials[blockIdx.x] = red[0];

    // ================= last-CTA finalize (losses + perplexity) =================
    __shared__ int sLast;
    __threadfence();
    if (tid == 0) sLast = (atomicAdd(&g_done, 1) == NCTAS - 1);
    __syncthreads();
    if (!sLast) return;
    __threadfence();   // acquire: all CTAs' partials/counts visible

    red[tid] = (tid < NCTAS) ? g_partials[tid] : 0.f;
    __syncthreads();
    for (int off = 256; off; off >>= 1) {
        if (tid < off) red[tid] += red[tid + off];
        __syncthreads();
    }
    if (tid == 0) {
        const float loss = red[0] / (float)((size_t)NV * DD);
        out[(size_t)NV + (size_t)NV * DD + 0] = loss;
        out[(size_t)NV + (size_t)NV * DD + 1] = loss;
    }
    __syncthreads();

    float e = 0.f;
    for (int k = tid; k < KC; k += 512) {
        const float p = (float)g_counts[k] * 0.1f;
        e += p * logf(p + 1e-10f);
    }
    red[tid] = e;
    __syncthreads();
    for (int off = 256; off; off >>= 1) {
        if (tid < off) red[tid] += red[tid + off];
        __syncthreads();
    }
    if (tid == 0) {
        out[(size_t)NV + (size_t)NV * DD + 2] = expf(-red[0]);
        g_done = 0;   // reset for next graph replay
    }
}

// ---------------------------------------------------------------------------
extern "C" void kernel_launch(void* const* d_in, const int* in_sizes, int n_in,
                              void* d_out, int out_size)
{
    const float* ze = (const float*)d_in[0];
    const float* cb = (const float*)d_in[1];
    float* out = (float*)d_out;

    cudaFuncSetAttribute(argmin_kernel,
                         cudaFuncAttributeMaxDynamicSharedMemorySize, SMEM_REQ);

    prep_kernel<<<2560 + 512, 256>>>(ze, cb);
    argmin_kernel<<<NCTAS, 512, SMEM_REQ>>>(ze, cb, out);
}